// round 12
// baseline (speedup 1.0000x reference)
#include <cuda_runtime.h>
#include <cuda_bf16.h>
#include <cstdint>

#define BB 131072
#define CC 256
#define DD 64
#define NSTEP 8
#define DTB 0.15f
#define EPSV 1e-4f
#define ROWS 128                  // per CTA (8 warps x 16 rows)
#define THREADS 256
#define NBLK (BB / ROWS)          // 1024

// SCALE_W = 2^13 (w in e4m3 range), SCALE_M = 2^6 (mu/r in e4m3 range)
// ---------------- SMEM layout ----------------
#define SM_B1 0                   // uint4[32 nt][32 lane]  (q0b0,q0b1,q1b0,q1b1) 16384
#define SM_B2 16384               // uint4[8 K][4 p][32 lane]                     16384
#define SM_QM 32768               // float2[256] = (cn2+eps, mu*64)                2048
#define SM_TOTAL 34816

static __device__ __forceinline__ uint32_t pack4_e4m3(float a, float b, float c, float d) {
    uint16_t lo, hi;
    asm("cvt.rn.satfinite.e4m3x2.f32 %0, %1, %2;" : "=h"(lo) : "f"(b), "f"(a));
    asm("cvt.rn.satfinite.e4m3x2.f32 %0, %1, %2;" : "=h"(hi) : "f"(d), "f"(c));
    return (uint32_t)lo | ((uint32_t)hi << 16);
}
static __device__ __forceinline__ void mma16832(
    float* c, const uint32_t* a, uint32_t b0, uint32_t b1)
{
    asm volatile(
        "mma.sync.aligned.m16n8k32.row.col.f32.e4m3.e4m3.f32 "
        "{%0,%1,%2,%3}, {%4,%5,%6,%7}, {%8,%9}, {%0,%1,%2,%3};"
        : "+f"(c[0]), "+f"(c[1]), "+f"(c[2]), "+f"(c[3])
        : "r"(a[0]), "r"(a[1]), "r"(a[2]), "r"(a[3]), "r"(b0), "r"(b1));
}
static __device__ __forceinline__ float qred(float v) {
    v += __shfl_xor_sync(0xFFFFFFFFu, v, 1);
    v += __shfl_xor_sync(0xFFFFFFFFu, v, 2);
    return v;
}

__global__ void __launch_bounds__(THREADS, 2) pm_field_mma_kernel(
    const float* __restrict__ z_in,
    const float* __restrict__ centers,
    const float* __restrict__ mus,
    float* __restrict__ out)
{
    extern __shared__ char smem[];
    uint4* B1 = (uint4*)(smem + SM_B1);
    uint4* B2 = (uint4*)(smem + SM_B2);

    const int tid  = threadIdx.x;
    const int wid  = tid >> 5;
    const int lane = tid & 31;
    const int m    = lane & 3;
    const int g    = lane >> 2;

    // ---- setup: e4m3 fragments from gmem (one-time, L2) ----
    // B1 (GEMM1): per n-tile nt, per k32-chunk q over d. k-byte 4m+i <-> d = 32q + L(m,i),
    // L(m,·) = {2m, 2m+1, 8+2m, 8+2m+1}; second reg: d += 16.
    for (int nt = 4 * wid; nt < 4 * wid + 4; nt++) {
        const float* p = centers + (8 * nt + g) * DD;
        uint4 v;
        uint32_t* vv = (uint32_t*)&v;
        #pragma unroll
        for (int q = 0; q < 2; q++) {
            vv[2*q]   = pack4_e4m3(p[32*q +      2*m], p[32*q +      2*m + 1],
                                   p[32*q +  8 + 2*m], p[32*q +  8 + 2*m + 1]);
            vv[2*q+1] = pack4_e4m3(p[32*q + 16 + 2*m], p[32*q + 16 + 2*m + 1],
                                   p[32*q + 24 + 2*m], p[32*q + 24 + 2*m + 1]);
        }
        B1[nt * 32 + lane] = v;
    }
    // B2 (GEMM2): per center-chunk K (32 centers), n-tile nt over d. k-byte 4m+i <-> center
    // 32K + L(m,i) (reg b1: +16). Same L — matches the epilogue's owned S-cols exactly.
    {
        const int K = wid;
        #pragma unroll
        for (int p2 = 0; p2 < 4; p2++) {
            const int d0 = 8 * (2 * p2) + g;
            const int d1 = 8 * (2 * p2 + 1) + g;
            const int cA = 32 * K + 2 * m;
            uint4 v;
            v.x = pack4_e4m3(centers[(cA     ) * DD + d0], centers[(cA +  1) * DD + d0],
                             centers[(cA +  8) * DD + d0], centers[(cA +  9) * DD + d0]);
            v.y = pack4_e4m3(centers[(cA + 16) * DD + d0], centers[(cA + 17) * DD + d0],
                             centers[(cA + 24) * DD + d0], centers[(cA + 25) * DD + d0]);
            v.z = pack4_e4m3(centers[(cA     ) * DD + d1], centers[(cA +  1) * DD + d1],
                             centers[(cA +  8) * DD + d1], centers[(cA +  9) * DD + d1]);
            v.w = pack4_e4m3(centers[(cA + 16) * DD + d1], centers[(cA + 17) * DD + d1],
                             centers[(cA + 24) * DD + d1], centers[(cA + 25) * DD + d1]);
            B2[(K * 4 + p2) * 32 + lane] = v;
        }
    }
    {   // (cn2+eps, mu*64)
        const int c = tid;   // THREADS == CC
        const float4* cr = (const float4*)(centers + c * DD);
        float s = 0.f;
        #pragma unroll
        for (int i = 0; i < DD / 4; i++) {
            float4 v = cr[i];
            s = fmaf(v.x, v.x, fmaf(v.y, v.y, fmaf(v.z, v.z, fmaf(v.w, v.w, s))));
        }
        *(float2*)(smem + SM_QM + c * 8) = make_float2(s + EPSV, mus[c] * 64.0f);
    }
    __syncthreads();
    // ==== no block syncs below — warps autonomous ====

    const size_t rbase = (size_t)blockIdx.x * ROWS + wid * 16 + g;
    float z0[16], z1[16];
    #pragma unroll
    for (int blk = 0; blk < 8; blk++) {
        float2 v;
        v = *(const float2*)(z_in + (rbase    ) * DD + 8 * blk + 2 * m); z0[2*blk]=v.x; z0[2*blk+1]=v.y;
        v = *(const float2*)(z_in + (rbase + 8) * DD + 8 * blk + 2 * m); z1[2*blk]=v.x; z1[2*blk+1]=v.y;
    }

    // ones column (n=0) B-fragment: e4m3 1.0 = 0x38, nonzero only for g==0 lanes
    const uint32_t bones = (g == 0) ? 0x38383838u : 0u;

    #pragma unroll 1
    for (int step = 0; step < NSTEP; step++) {
        float s0 = 0.f, s1 = 0.f;
        #pragma unroll
        for (int j = 0; j < 16; j++) {
            s0 = fmaf(z0[j], z0[j], s0);
            s1 = fmaf(z1[j], z1[j], s1);
        }
        s0 = qred(s0); s1 = qred(s1);

        // A-frags of GEMM1 (e4m3): af[q][0]=row g k4m.., [1]=row g+8, [2]=+16, [3]
        uint32_t af[2][4];
        #pragma unroll
        for (int q = 0; q < 2; q++) {
            af[q][0] = pack4_e4m3(z0[8*q+0], z0[8*q+1], z0[8*q+2], z0[8*q+3]);
            af[q][1] = pack4_e4m3(z1[8*q+0], z1[8*q+1], z1[8*q+2], z1[8*q+3]);
            af[q][2] = pack4_e4m3(z0[8*q+4], z0[8*q+5], z0[8*q+6], z0[8*q+7]);
            af[q][3] = pack4_e4m3(z1[8*q+4], z1[8*q+5], z1[8*q+6], z1[8*q+7]);
        }

        float gacc[8][4];
        #pragma unroll
        for (int i = 0; i < 8; i++)
            gacc[i][0] = gacc[i][1] = gacc[i][2] = gacc[i][3] = 0.f;
        float swacc[4] = {0.f, 0.f, 0.f, 0.f};   // Σ(w*8192) via W@ones
        float naacc[4] = {0.f, 0.f, 0.f, 0.f};   // Σ(m*64)   via M@ones

        #pragma unroll 1
        for (int K = 0; K < 8; K++) {
            uint32_t wa[4], ma[4];

            #pragma unroll
            for (int h = 0; h < 2; h++) {
                uint4 u0 = B1[(4 * K + 2 * h    ) * 32 + lane];
                uint4 u1 = B1[(4 * K + 2 * h + 1) * 32 + lane];
                float A0[4] = {0.f, 0.f, 0.f, 0.f};
                float A1[4] = {0.f, 0.f, 0.f, 0.f};
                mma16832(A0, af[0], u0.x, u0.y);
                mma16832(A1, af[0], u1.x, u1.y);
                mma16832(A0, af[1], u0.z, u0.w);
                mma16832(A1, af[1], u1.z, u1.w);

                const int cb = 32 * K + 16 * h + 2 * m;
                const float4 q01 = *(const float4*)(smem + SM_QM + cb * 8);        // cols cb, cb+1
                const float4 q23 = *(const float4*)(smem + SM_QM + (cb + 8) * 8);  // cols cb+8, cb+9

                // 8 values: (A0c0,A0c1,A1c0,A1c1) x rows (g, g+8)
                float t0 = fmaf(-2.f, A0[0], s0 + q01.x);
                float t1 = fmaf(-2.f, A0[1], s0 + q01.z);
                float t2 = fmaf(-2.f, A1[0], s0 + q23.x);
                float t3 = fmaf(-2.f, A1[1], s0 + q23.z);
                float t4 = fmaf(-2.f, A0[2], s1 + q01.x);
                float t5 = fmaf(-2.f, A0[3], s1 + q01.z);
                float t6 = fmaf(-2.f, A1[2], s1 + q23.x);
                float t7 = fmaf(-2.f, A1[3], s1 + q23.z);
                float i0 = rsqrtf(t0), i1 = rsqrtf(t1), i2 = rsqrtf(t2), i3 = rsqrtf(t3);
                float i4 = rsqrtf(t4), i5 = rsqrtf(t5), i6 = rsqrtf(t6), i7 = rsqrtf(t7);
                float m0 = q01.y * i0, m1 = q01.w * i1, m2 = q23.y * i2, m3 = q23.w * i3;
                float m4 = q01.y * i4, m5 = q01.w * i5, m6 = q23.y * i6, m7 = q23.w * i7;
                // w*8192 = (m*64) * i^2 * 128
                float w0 = m0*i0*i0*128.f, w1 = m1*i1*i1*128.f, w2 = m2*i2*i2*128.f, w3 = m3*i3*i3*128.f;
                float w4 = m4*i4*i4*128.f, w5 = m5*i5*i5*128.f, w6 = m6*i6*i6*128.f, w7 = m7*i7*i7*128.f;
                wa[2*h]     = pack4_e4m3(w0, w1, w2, w3);
                wa[2*h + 1] = pack4_e4m3(w4, w5, w6, w7);
                ma[2*h]     = pack4_e4m3(m0, m1, m2, m3);
                ma[2*h + 1] = pack4_e4m3(m4, m5, m6, m7);
            }

            // sums on tensor pipe (col 0)
            mma16832(swacc, wa, bones, bones);
            mma16832(naacc, ma, bones, bones);

            // GEMM2: G += W_chunk @ centers
            {
                uint4 v0 = B2[(K * 4 + 0) * 32 + lane];
                uint4 v1 = B2[(K * 4 + 1) * 32 + lane];
                mma16832(gacc[0], wa, v0.x, v0.y);
                mma16832(gacc[1], wa, v0.z, v0.w);
                mma16832(gacc[2], wa, v1.x, v1.y);
                mma16832(gacc[3], wa, v1.z, v1.w);
            }
            {
                uint4 v2 = B2[(K * 4 + 2) * 32 + lane];
                uint4 v3 = B2[(K * 4 + 3) * 32 + lane];
                mma16832(gacc[4], wa, v2.x, v2.y);
                mma16832(gacc[5], wa, v2.z, v2.w);
                mma16832(gacc[6], wa, v3.x, v3.y);
                mma16832(gacc[7], wa, v3.z, v3.w);
            }
        }

        // broadcast col-0 sums within quad; undo scales (G,sw: 2^13; na: 2^6)
        const int qbase = lane & 28;
        const float sw0 = __shfl_sync(0xFFFFFFFFu, swacc[0], qbase);
        const float sw1 = __shfl_sync(0xFFFFFFFFu, swacc[2], qbase);
        const float na0 = __shfl_sync(0xFFFFFFFFu, naacc[0], qbase);
        const float na1 = __shfl_sync(0xFFFFFFFFu, naacc[2], qbase);

        const float c0f = (DTB / 8192.0f) / fmaf(na0, 0.015625f, 1.0f);
        const float c1f = (DTB / 8192.0f) / fmaf(na1, 0.015625f, 1.0f);
        #pragma unroll
        for (int nt = 0; nt < 8; nt++) {
            float u;
            u = fmaf(c0f, fmaf(-sw0, z0[2*nt],   gacc[nt][0]), z0[2*nt]);   z0[2*nt]   = fminf(fmaxf(u,-3.f),3.f);
            u = fmaf(c0f, fmaf(-sw0, z0[2*nt+1], gacc[nt][1]), z0[2*nt+1]); z0[2*nt+1] = fminf(fmaxf(u,-3.f),3.f);
            u = fmaf(c1f, fmaf(-sw1, z1[2*nt],   gacc[nt][2]), z1[2*nt]);   z1[2*nt]   = fminf(fmaxf(u,-3.f),3.f);
            u = fmaf(c1f, fmaf(-sw1, z1[2*nt+1], gacc[nt][3]), z1[2*nt+1]); z1[2*nt+1] = fminf(fmaxf(u,-3.f),3.f);
        }
    }

    #pragma unroll
    for (int blk = 0; blk < 8; blk++) {
        *(float2*)(out + (rbase    ) * DD + 8*blk + 2*m) = make_float2(z0[2*blk], z0[2*blk+1]);
        *(float2*)(out + (rbase + 8) * DD + 8*blk + 2*m) = make_float2(z1[2*blk], z1[2*blk+1]);
    }
}

extern "C" void kernel_launch(void* const* d_in, const int* in_sizes, int n_in,
                              void* d_out, int out_size) {
    (void)in_sizes; (void)n_in; (void)out_size;
    const float* z       = (const float*)d_in[0];
    const float* centers = (const float*)d_in[1];
    const float* mus     = (const float*)d_in[2];
    float* out           = (float*)d_out;

    static bool attr_set = false;
    if (!attr_set) {
        cudaFuncSetAttribute(pm_field_mma_kernel,
                             cudaFuncAttributeMaxDynamicSharedMemorySize, SM_TOTAL);
        attr_set = true;
    }
    pm_field_mma_kernel<<<NBLK, THREADS, SM_TOTAL>>>(z, centers, mus, out);
}

// round 13
// speedup vs baseline: 1.1563x; 1.1563x over previous
#include <cuda_runtime.h>
#include <cuda_bf16.h>
#include <cstdint>

#define BB 131072
#define CC 256
#define DD 64
#define NSTEP 8
#define DTB 0.15f
#define EPSV 1e-4f
#define ROWS 128                  // per CTA (8 warps x 16 rows)
#define THREADS 256
#define NBLK (BB / ROWS)          // 1024

// ---------------- SMEM layout ----------------
#define SM_B1  0                  // fp8 GEMM1 B: uint4[32 nt][32 lane]          16384
#define SM_B2Q 16384              // bf16 GEMM2 B: uint4[16 KT][4 ntp][32 lane]  32768
#define SM_QM  49152              // float2[256] = (cn2+eps, mu)                  2048
#define SM_TOTAL 51200

static __device__ __forceinline__ uint32_t pack_bf16x2(float a, float b) {
    uint32_t r;
    asm("cvt.rn.bf16x2.f32 %0, %1, %2;" : "=r"(r) : "f"(b), "f"(a));
    return r;
}
static __device__ __forceinline__ uint32_t pack4_e4m3(float a, float b, float c, float d) {
    uint16_t lo, hi;
    asm("cvt.rn.satfinite.e4m3x2.f32 %0, %1, %2;" : "=h"(lo) : "f"(b), "f"(a));
    asm("cvt.rn.satfinite.e4m3x2.f32 %0, %1, %2;" : "=h"(hi) : "f"(d), "f"(c));
    return (uint32_t)lo | ((uint32_t)hi << 16);
}
static __device__ __forceinline__ void mma16816(
    float* c, uint32_t a0, uint32_t a1, uint32_t a2, uint32_t a3,
    uint32_t b0, uint32_t b1)
{
    asm volatile(
        "mma.sync.aligned.m16n8k16.row.col.f32.bf16.bf16.f32 "
        "{%0,%1,%2,%3}, {%4,%5,%6,%7}, {%8,%9}, {%0,%1,%2,%3};"
        : "+f"(c[0]), "+f"(c[1]), "+f"(c[2]), "+f"(c[3])
        : "r"(a0), "r"(a1), "r"(a2), "r"(a3), "r"(b0), "r"(b1));
}
static __device__ __forceinline__ void mma16832(
    float* c, const uint32_t* a, uint32_t b0, uint32_t b1)
{
    asm volatile(
        "mma.sync.aligned.m16n8k32.row.col.f32.e4m3.e4m3.f32 "
        "{%0,%1,%2,%3}, {%4,%5,%6,%7}, {%8,%9}, {%0,%1,%2,%3};"
        : "+f"(c[0]), "+f"(c[1]), "+f"(c[2]), "+f"(c[3])
        : "r"(a[0]), "r"(a[1]), "r"(a[2]), "r"(a[3]), "r"(b0), "r"(b1));
}
static __device__ __forceinline__ float qred(float v) {
    v += __shfl_xor_sync(0xFFFFFFFFu, v, 1);
    v += __shfl_xor_sync(0xFFFFFFFFu, v, 2);
    return v;
}

__global__ void __launch_bounds__(THREADS, 2) pm_field_mma_kernel(
    const float* __restrict__ z_in,
    const float* __restrict__ centers,
    const float* __restrict__ mus,
    float* __restrict__ out)
{
    extern __shared__ char smem[];
    uint4* B1  = (uint4*)(smem + SM_B1);
    uint4* B2q = (uint4*)(smem + SM_B2Q);

    const int tid  = threadIdx.x;
    const int wid  = tid >> 5;
    const int lane = tid & 31;
    const int m    = lane & 3;
    const int g    = lane >> 2;

    // ---- setup ----
    // B1 (fp8, GEMM1): per n-tile nt, uint4 = (q0:b0,b1, q1:b0,b1).
    // k-byte 4m+i of chunk q <-> d = 32q + L(m,i), L = {2m,2m+1,8+2m,9+2m}; b1: d+16.
    // Same permuted d-order used by the z A-frag packs below — consistent, so valid.
    for (int nt = 4 * wid; nt < 4 * wid + 4; nt++) {
        const float* p = centers + (8 * nt + g) * DD;
        uint4 v;
        uint32_t* vv = (uint32_t*)&v;
        #pragma unroll
        for (int q = 0; q < 2; q++) {
            vv[2*q]   = pack4_e4m3(p[32*q +      2*m], p[32*q +      2*m + 1],
                                   p[32*q +  8 + 2*m], p[32*q +  8 + 2*m + 1]);
            vv[2*q+1] = pack4_e4m3(p[32*q + 16 + 2*m], p[32*q + 16 + 2*m + 1],
                                   p[32*q + 24 + 2*m], p[32*q + 24 + 2*m + 1]);
        }
        B1[nt * 32 + lane] = v;
    }
    // B2 (bf16, GEMM2): unchanged from R11
    for (int KT = 2 * wid; KT < 2 * wid + 2; KT++) {
        const int c0 = 16 * KT + 2 * m;
        #pragma unroll
        for (int ntp = 0; ntp < 4; ntp++) {
            const int d0 = 16 * ntp + g;
            uint4 v;
            v.x = pack_bf16x2(centers[(c0    ) * DD + d0], centers[(c0 + 1) * DD + d0]);
            v.y = pack_bf16x2(centers[(c0 + 8) * DD + d0], centers[(c0 + 9) * DD + d0]);
            v.z = pack_bf16x2(centers[(c0    ) * DD + d0 + 8], centers[(c0 + 1) * DD + d0 + 8]);
            v.w = pack_bf16x2(centers[(c0 + 8) * DD + d0 + 8], centers[(c0 + 9) * DD + d0 + 8]);
            B2q[(KT * 4 + ntp) * 32 + lane] = v;
        }
    }
    {
        const int c = tid;   // THREADS == CC
        const float4* cr = (const float4*)(centers + c * DD);
        float s = 0.f;
        #pragma unroll
        for (int i = 0; i < DD / 4; i++) {
            float4 v = cr[i];
            s = fmaf(v.x, v.x, fmaf(v.y, v.y, fmaf(v.z, v.z, fmaf(v.w, v.w, s))));
        }
        *(float2*)(smem + SM_QM + c * 8) = make_float2(s + EPSV, mus[c]);
    }
    __syncthreads();
    // ==== no block syncs below — warps autonomous ====

    const size_t rbase = (size_t)blockIdx.x * ROWS + wid * 16 + g;
    float z0[16], z1[16];
    #pragma unroll
    for (int blk = 0; blk < 8; blk++) {
        float2 v;
        v = *(const float2*)(z_in + (rbase    ) * DD + 8 * blk + 2 * m); z0[2*blk]=v.x; z0[2*blk+1]=v.y;
        v = *(const float2*)(z_in + (rbase + 8) * DD + 8 * blk + 2 * m); z1[2*blk]=v.x; z1[2*blk+1]=v.y;
    }

    // ones column (bf16) for the sum-GEMMs: nonzero only on g==0 lanes
    const uint32_t bones = (g == 0) ? 0x3F803F80u : 0u;

    #pragma unroll 1
    for (int step = 0; step < NSTEP; step++) {
        float s0 = 0.f, s1 = 0.f;
        #pragma unroll
        for (int j = 0; j < 16; j++) {
            s0 = fmaf(z0[j], z0[j], s0);
            s1 = fmaf(z1[j], z1[j], s1);
        }
        s0 = qred(s0); s1 = qred(s1);

        // fp8 A-frags of GEMM1: af[q] covers z-dims 32q..32q+31 in the permuted order
        uint32_t af[2][4];
        #pragma unroll
        for (int q = 0; q < 2; q++) {
            af[q][0] = pack4_e4m3(z0[8*q+0], z0[8*q+1], z0[8*q+2], z0[8*q+3]);
            af[q][1] = pack4_e4m3(z1[8*q+0], z1[8*q+1], z1[8*q+2], z1[8*q+3]);
            af[q][2] = pack4_e4m3(z0[8*q+4], z0[8*q+5], z0[8*q+6], z0[8*q+7]);
            af[q][3] = pack4_e4m3(z1[8*q+4], z1[8*q+5], z1[8*q+6], z1[8*q+7]);
        }

        float gacc[8][4];
        #pragma unroll
        for (int i = 0; i < 8; i++)
            gacc[i][0] = gacc[i][1] = gacc[i][2] = gacc[i][3] = 0.f;
        float swacc[4] = {0.f, 0.f, 0.f, 0.f};   // Σw via W@ones (bf16)
        float naacc[4] = {0.f, 0.f, 0.f, 0.f};   // Σm via M@ones (bf16)

        #pragma unroll 2
        for (int KT = 0; KT < 16; KT++) {
            float aA[2][4];
            #pragma unroll
            for (int i = 0; i < 2; i++)
                aA[i][0] = aA[i][1] = aA[i][2] = aA[i][3] = 0.f;

            {   // GEMM1 fp8: 2 n-tiles x 2 k32-chunks = 4 mma, 2 LDS.128
                uint4 v0 = B1[(2 * KT    ) * 32 + lane];
                uint4 v1 = B1[(2 * KT + 1) * 32 + lane];
                mma16832(aA[0], af[0], v0.x, v0.y);
                mma16832(aA[1], af[0], v1.x, v1.y);
                mma16832(aA[0], af[1], v0.z, v0.w);
                mma16832(aA[1], af[1], v1.z, v1.w);
            }

            // B2 prefetch before epilogue (latency hides under rsqrt chain)
            uint4 b2_0 = B2q[(KT * 4 + 0) * 32 + lane];
            uint4 b2_1 = B2q[(KT * 4 + 1) * 32 + lane];
            uint4 b2_2 = B2q[(KT * 4 + 2) * 32 + lane];
            uint4 b2_3 = B2q[(KT * 4 + 3) * 32 + lane];

            const int c0 = 16 * KT + 2 * m;
            const float4 q01 = *(const float4*)(smem + SM_QM + c0 * 8);
            const float4 q23 = *(const float4*)(smem + SM_QM + (c0 + 8) * 8);

            uint32_t wa[4], ma[4];
            #pragma unroll
            for (int half = 0; half < 2; half++) {
                const float4 P = half ? q23 : q01;   // (cn2e_lo, mu_lo, cn2e_hi, mu_hi)
                float t0 = fmaf(-2.f, aA[half][0], s0 + P.x);
                float t1 = fmaf(-2.f, aA[half][1], s0 + P.z);
                float t2 = fmaf(-2.f, aA[half][2], s1 + P.x);
                float t3 = fmaf(-2.f, aA[half][3], s1 + P.z);
                float i0 = rsqrtf(t0), i1 = rsqrtf(t1), i2 = rsqrtf(t2), i3 = rsqrtf(t3);
                float m0 = P.y * i0, m1 = P.w * i1, m2 = P.y * i2, m3 = P.w * i3;
                float w0 = m0*i0*i0, w1 = m1*i1*i1, w2 = m2*i2*i2, w3 = m3*i3*i3;
                wa[2*half]     = pack_bf16x2(w0, w1);
                wa[2*half + 1] = pack_bf16x2(w2, w3);
                ma[2*half]     = pack_bf16x2(m0, m1);
                ma[2*half + 1] = pack_bf16x2(m2, m3);
            }

            // sums on the tensor pipe: col 0 of (W|M) @ ones
            mma16816(swacc, wa[0], wa[1], wa[2], wa[3], bones, bones);
            mma16816(naacc, ma[0], ma[1], ma[2], ma[3], bones, bones);

            mma16816(gacc[0], wa[0], wa[1], wa[2], wa[3], b2_0.x, b2_0.y);
            mma16816(gacc[1], wa[0], wa[1], wa[2], wa[3], b2_0.z, b2_0.w);
            mma16816(gacc[2], wa[0], wa[1], wa[2], wa[3], b2_1.x, b2_1.y);
            mma16816(gacc[3], wa[0], wa[1], wa[2], wa[3], b2_1.z, b2_1.w);
            mma16816(gacc[4], wa[0], wa[1], wa[2], wa[3], b2_2.x, b2_2.y);
            mma16816(gacc[5], wa[0], wa[1], wa[2], wa[3], b2_2.z, b2_2.w);
            mma16816(gacc[6], wa[0], wa[1], wa[2], wa[3], b2_3.x, b2_3.y);
            mma16816(gacc[7], wa[0], wa[1], wa[2], wa[3], b2_3.z, b2_3.w);
        }

        // broadcast col-0 sums within quad
        const int qbase = lane & 28;
        const float sw0 = __shfl_sync(0xFFFFFFFFu, swacc[0], qbase);
        const float sw1 = __shfl_sync(0xFFFFFFFFu, swacc[2], qbase);
        const float na0 = __shfl_sync(0xFFFFFFFFu, naacc[0], qbase);
        const float na1 = __shfl_sync(0xFFFFFFFFu, naacc[2], qbase);

        const float c0f = DTB / (1.f + na0);
        const float c1f = DTB / (1.f + na1);
        #pragma unroll
        for (int nt = 0; nt < 8; nt++) {
            float u;
            u = fmaf(c0f, fmaf(-sw0, z0[2*nt],   gacc[nt][0]), z0[2*nt]);   z0[2*nt]   = fminf(fmaxf(u,-3.f),3.f);
            u = fmaf(c0f, fmaf(-sw0, z0[2*nt+1], gacc[nt][1]), z0[2*nt+1]); z0[2*nt+1] = fminf(fmaxf(u,-3.f),3.f);
            u = fmaf(c1f, fmaf(-sw1, z1[2*nt],   gacc[nt][2]), z1[2*nt]);   z1[2*nt]   = fminf(fmaxf(u,-3.f),3.f);
            u = fmaf(c1f, fmaf(-sw1, z1[2*nt+1], gacc[nt][3]), z1[2*nt+1]); z1[2*nt+1] = fminf(fmaxf(u,-3.f),3.f);
        }
    }

    #pragma unroll
    for (int blk = 0; blk < 8; blk++) {
        *(float2*)(out + (rbase    ) * DD + 8*blk + 2*m) = make_float2(z0[2*blk], z0[2*blk+1]);
        *(float2*)(out + (rbase + 8) * DD + 8*blk + 2*m) = make_float2(z1[2*blk], z1[2*blk+1]);
    }
}

extern "C" void kernel_launch(void* const* d_in, const int* in_sizes, int n_in,
                              void* d_out, int out_size) {
    (void)in_sizes; (void)n_in; (void)out_size;
    const float* z       = (const float*)d_in[0];
    const float* centers = (const float*)d_in[1];
    const float* mus     = (const float*)d_in[2];
    float* out           = (float*)d_out;

    static bool attr_set = false;
    if (!attr_set) {
        cudaFuncSetAttribute(pm_field_mma_kernel,
                             cudaFuncAttributeMaxDynamicSharedMemorySize, SM_TOTAL);
        attr_set = true;
    }
    pm_field_mma_kernel<<<NBLK, THREADS, SM_TOTAL>>>(z, centers, mus, out);
}

// round 14
// speedup vs baseline: 1.2707x; 1.0989x over previous
#include <cuda_runtime.h>
#include <cuda_bf16.h>
#include <cstdint>

#define BB 131072
#define CC 256
#define DD 64
#define NSTEP 8
#define DTB 0.15f
#define EPSV 1e-4f
#define ROWS 128                  // per CTA (8 warps x 16 rows)
#define THREADS 256
#define NBLK (BB / ROWS)          // 1024

// ---------------- SMEM layout ----------------
#define SM_B1Q 0                  // uint4[32 nt][2 ktp][32 lane]  32768
#define SM_B2Q 32768              // uint4[16 KT][4 ntp][32 lane]  32768
#define SM_QM  65536              // float2[256] = (cn2+eps, mu)    2048
#define SM_TOTAL 67584

static __device__ __forceinline__ uint32_t pack_bf16x2(float a, float b) {
    uint32_t r;
    asm("cvt.rn.bf16x2.f32 %0, %1, %2;" : "=r"(r) : "f"(b), "f"(a));
    return r;
}
static __device__ __forceinline__ void mma16816(
    float* c, uint32_t a0, uint32_t a1, uint32_t a2, uint32_t a3,
    uint32_t b0, uint32_t b1)
{
    asm volatile(
        "mma.sync.aligned.m16n8k16.row.col.f32.bf16.bf16.f32 "
        "{%0,%1,%2,%3}, {%4,%5,%6,%7}, {%8,%9}, {%0,%1,%2,%3};"
        : "+f"(c[0]), "+f"(c[1]), "+f"(c[2]), "+f"(c[3])
        : "r"(a0), "r"(a1), "r"(a2), "r"(a3), "r"(b0), "r"(b1));
}
static __device__ __forceinline__ float qred(float v) {
    v += __shfl_xor_sync(0xFFFFFFFFu, v, 1);
    v += __shfl_xor_sync(0xFFFFFFFFu, v, 2);
    return v;
}

__global__ void __launch_bounds__(THREADS, 2) pm_field_mma_kernel(
    const float* __restrict__ z_in,
    const float* __restrict__ centers,
    const float* __restrict__ mus,
    float* __restrict__ out)
{
    extern __shared__ char smem[];
    uint4* B1q = (uint4*)(smem + SM_B1Q);
    uint4* B2q = (uint4*)(smem + SM_B2Q);

    const int tid  = threadIdx.x;
    const int wid  = tid >> 5;
    const int lane = tid & 31;
    const int m    = lane & 3;
    const int g    = lane >> 2;

    // ---- setup: fragments straight from gmem ----
    for (int nt = 4 * wid; nt < 4 * wid + 4; nt++) {
        const float* p = centers + (8 * nt + g) * DD;
        #pragma unroll
        for (int ktp = 0; ktp < 2; ktp++) {
            const int d0 = 32 * ktp + 2 * m;
            float2 f0 = *(const float2*)(p + d0);
            float2 f1 = *(const float2*)(p + d0 + 8);
            float2 f2 = *(const float2*)(p + d0 + 16);
            float2 f3 = *(const float2*)(p + d0 + 24);
            uint4 v;
            v.x = pack_bf16x2(f0.x, f0.y);
            v.y = pack_bf16x2(f1.x, f1.y);
            v.z = pack_bf16x2(f2.x, f2.y);
            v.w = pack_bf16x2(f3.x, f3.y);
            B1q[(nt * 2 + ktp) * 32 + lane] = v;
        }
    }
    for (int KT = 2 * wid; KT < 2 * wid + 2; KT++) {
        const int c0 = 16 * KT + 2 * m;
        #pragma unroll
        for (int ntp = 0; ntp < 4; ntp++) {
            const int d0 = 16 * ntp + g;
            uint4 v;
            v.x = pack_bf16x2(centers[(c0    ) * DD + d0], centers[(c0 + 1) * DD + d0]);
            v.y = pack_bf16x2(centers[(c0 + 8) * DD + d0], centers[(c0 + 9) * DD + d0]);
            v.z = pack_bf16x2(centers[(c0    ) * DD + d0 + 8], centers[(c0 + 1) * DD + d0 + 8]);
            v.w = pack_bf16x2(centers[(c0 + 8) * DD + d0 + 8], centers[(c0 + 9) * DD + d0 + 8]);
            B2q[(KT * 4 + ntp) * 32 + lane] = v;
        }
    }
    {
        const int c = tid;   // THREADS == CC
        const float4* cr = (const float4*)(centers + c * DD);
        float s = 0.f;
        #pragma unroll
        for (int i = 0; i < DD / 4; i++) {
            float4 v = cr[i];
            s = fmaf(v.x, v.x, fmaf(v.y, v.y, fmaf(v.z, v.z, fmaf(v.w, v.w, s))));
        }
        *(float2*)(smem + SM_QM + c * 8) = make_float2(s + EPSV, mus[c]);
    }
    __syncthreads();
    // ==== no block syncs below — warps autonomous ====

    const size_t rbase = (size_t)blockIdx.x * ROWS + wid * 16 + g;
    float z0[16], z1[16];
    #pragma unroll
    for (int blk = 0; blk < 8; blk++) {
        float2 v;
        v = *(const float2*)(z_in + (rbase    ) * DD + 8 * blk + 2 * m); z0[2*blk]=v.x; z0[2*blk+1]=v.y;
        v = *(const float2*)(z_in + (rbase + 8) * DD + 8 * blk + 2 * m); z1[2*blk]=v.x; z1[2*blk+1]=v.y;
    }

    // constant ones B-fragment (column n=0): nonzero only on lanes with g==0
    const uint32_t bones = (g == 0) ? 0x3F803F80u : 0u;

    #pragma unroll 1
    for (int step = 0; step < NSTEP; step++) {
        float s0 = 0.f, s1 = 0.f;
        #pragma unroll
        for (int j = 0; j < 16; j++) {
            s0 = fmaf(z0[j], z0[j], s0);
            s1 = fmaf(z1[j], z1[j], s1);
        }
        s0 = qred(s0); s1 = qred(s1);

        uint32_t af[4][4];
        #pragma unroll
        for (int kt = 0; kt < 4; kt++) {
            af[kt][0] = pack_bf16x2(z0[4*kt+0], z0[4*kt+1]);
            af[kt][1] = pack_bf16x2(z1[4*kt+0], z1[4*kt+1]);
            af[kt][2] = pack_bf16x2(z0[4*kt+2], z0[4*kt+3]);
            af[kt][3] = pack_bf16x2(z1[4*kt+2], z1[4*kt+3]);
        }

        float gacc[8][4];
        #pragma unroll
        for (int i = 0; i < 8; i++)
            gacc[i][0] = gacc[i][1] = gacc[i][2] = gacc[i][3] = 0.f;
        float swacc[4] = {0.f, 0.f, 0.f, 0.f};   // Σw via W @ ones (tensor)
        float na0 = 0.f, na1 = 0.f;              // Σ(mu/r) scalar (fma pipe)

        // rotated prefetch of B1: chunk KT's fragments loaded one iteration ahead
        uint4 p0a = B1q[0 * 32 + lane];
        uint4 p0b = B1q[1 * 32 + lane];
        uint4 p1a = B1q[2 * 32 + lane];
        uint4 p1b = B1q[3 * 32 + lane];

        #pragma unroll 2
        for (int KT = 0; KT < 16; KT++) {
            const uint4 u0a = p0a, u0b = p0b, u1a = p1a, u1b = p1b;
            if (KT < 15) {
                p0a = B1q[((2 * KT + 2) * 2 + 0) * 32 + lane];
                p0b = B1q[((2 * KT + 2) * 2 + 1) * 32 + lane];
                p1a = B1q[((2 * KT + 3) * 2 + 0) * 32 + lane];
                p1b = B1q[((2 * KT + 3) * 2 + 1) * 32 + lane];
            }

            float aA[2][4];
            #pragma unroll
            for (int i = 0; i < 2; i++)
                aA[i][0] = aA[i][1] = aA[i][2] = aA[i][3] = 0.f;

            mma16816(aA[0], af[0][0], af[0][1], af[0][2], af[0][3], u0a.x, u0a.y);
            mma16816(aA[1], af[0][0], af[0][1], af[0][2], af[0][3], u1a.x, u1a.y);
            mma16816(aA[0], af[1][0], af[1][1], af[1][2], af[1][3], u0a.z, u0a.w);
            mma16816(aA[1], af[1][0], af[1][1], af[1][2], af[1][3], u1a.z, u1a.w);
            mma16816(aA[0], af[2][0], af[2][1], af[2][2], af[2][3], u0b.x, u0b.y);
            mma16816(aA[1], af[2][0], af[2][1], af[2][2], af[2][3], u1b.x, u1b.y);
            mma16816(aA[0], af[3][0], af[3][1], af[3][2], af[3][3], u0b.z, u0b.w);
            mma16816(aA[1], af[3][0], af[3][1], af[3][2], af[3][3], u1b.z, u1b.w);

            // B2 prefetch before epilogue (latency hides under rsqrt chain)
            uint4 b2_0 = B2q[(KT * 4 + 0) * 32 + lane];
            uint4 b2_1 = B2q[(KT * 4 + 1) * 32 + lane];
            uint4 b2_2 = B2q[(KT * 4 + 2) * 32 + lane];
            uint4 b2_3 = B2q[(KT * 4 + 3) * 32 + lane];

            const int c0 = 16 * KT + 2 * m;
            const float4 q01 = *(const float4*)(smem + SM_QM + c0 * 8);
            const float4 q23 = *(const float4*)(smem + SM_QM + (c0 + 8) * 8);

            uint32_t wa[4];
            #pragma unroll
            for (int half = 0; half < 2; half++) {
                const float4 P = half ? q23 : q01;   // (cn2e_lo, mu_lo, cn2e_hi, mu_hi)
                float t0 = fmaf(-2.f, aA[half][0], s0 + P.x);
                float t1 = fmaf(-2.f, aA[half][1], s0 + P.z);
                float t2 = fmaf(-2.f, aA[half][2], s1 + P.x);
                float t3 = fmaf(-2.f, aA[half][3], s1 + P.z);
                float i0 = rsqrtf(t0), i1 = rsqrtf(t1), i2 = rsqrtf(t2), i3 = rsqrtf(t3);
                float m0 = P.y * i0, m1 = P.w * i1, m2 = P.y * i2, m3 = P.w * i3;
                na0 += m0 + m1;  na1 += m2 + m3;
                float w0 = m0*i0*i0, w1 = m1*i1*i1, w2 = m2*i2*i2, w3 = m3*i3*i3;
                wa[2*half]     = pack_bf16x2(w0, w1);
                wa[2*half + 1] = pack_bf16x2(w2, w3);
            }

            // Σw on the tensor pipe (col 0)
            mma16816(swacc, wa[0], wa[1], wa[2], wa[3], bones, bones);

            mma16816(gacc[0], wa[0], wa[1], wa[2], wa[3], b2_0.x, b2_0.y);
            mma16816(gacc[1], wa[0], wa[1], wa[2], wa[3], b2_0.z, b2_0.w);
            mma16816(gacc[2], wa[0], wa[1], wa[2], wa[3], b2_1.x, b2_1.y);
            mma16816(gacc[3], wa[0], wa[1], wa[2], wa[3], b2_1.z, b2_1.w);
            mma16816(gacc[4], wa[0], wa[1], wa[2], wa[3], b2_2.x, b2_2.y);
            mma16816(gacc[5], wa[0], wa[1], wa[2], wa[3], b2_2.z, b2_2.w);
            mma16816(gacc[6], wa[0], wa[1], wa[2], wa[3], b2_3.x, b2_3.y);
            mma16816(gacc[7], wa[0], wa[1], wa[2], wa[3], b2_3.z, b2_3.w);
        }

        // reductions: sw from GEMM col 0 (broadcast), na scalar quad-reduce
        const int qbase = lane & 28;
        const float sw0 = __shfl_sync(0xFFFFFFFFu, swacc[0], qbase);
        const float sw1 = __shfl_sync(0xFFFFFFFFu, swacc[2], qbase);
        na0 = qred(na0);
        na1 = qred(na1);

        const float c0f = DTB / (1.f + na0);
        const float c1f = DTB / (1.f + na1);
        #pragma unroll
        for (int nt = 0; nt < 8; nt++) {
            float u;
            u = fmaf(c0f, fmaf(-sw0, z0[2*nt],   gacc[nt][0]), z0[2*nt]);   z0[2*nt]   = fminf(fmaxf(u,-3.f),3.f);
            u = fmaf(c0f, fmaf(-sw0, z0[2*nt+1], gacc[nt][1]), z0[2*nt+1]); z0[2*nt+1] = fminf(fmaxf(u,-3.f),3.f);
            u = fmaf(c1f, fmaf(-sw1, z1[2*nt],   gacc[nt][2]), z1[2*nt]);   z1[2*nt]   = fminf(fmaxf(u,-3.f),3.f);
            u = fmaf(c1f, fmaf(-sw1, z1[2*nt+1], gacc[nt][3]), z1[2*nt+1]); z1[2*nt+1] = fminf(fmaxf(u,-3.f),3.f);
        }
    }

    #pragma unroll
    for (int blk = 0; blk < 8; blk++) {
        *(float2*)(out + (rbase    ) * DD + 8*blk + 2*m) = make_float2(z0[2*blk], z0[2*blk+1]);
        *(float2*)(out + (rbase + 8) * DD + 8*blk + 2*m) = make_float2(z1[2*blk], z1[2*blk+1]);
    }
}

extern "C" void kernel_launch(void* const* d_in, const int* in_sizes, int n_in,
                              void* d_out, int out_size) {
    (void)in_sizes; (void)n_in; (void)out_size;
    const float* z       = (const float*)d_in[0];
    const float* centers = (const float*)d_in[1];
    const float* mus     = (const float*)d_in[2];
    float* out           = (float*)d_out;

    static bool attr_set = false;
    if (!attr_set) {
        cudaFuncSetAttribute(pm_field_mma_kernel,
                             cudaFuncAttributeMaxDynamicSharedMemorySize, SM_TOTAL);
        attr_set = true;
    }
    pm_field_mma_kernel<<<NBLK, THREADS, SM_TOTAL>>>(z, centers, mus, out);
}

// round 15
// speedup vs baseline: 1.2730x; 1.0018x over previous
#include <cuda_runtime.h>
#include <cuda_bf16.h>
#include <cstdint>

#define BB 131072
#define CC 256
#define DD 64
#define NSTEP 8
#define DTB 0.15f
#define EPSV 1e-4f
#define ROWS 128                  // per CTA (8 warps x 16 rows)
#define THREADS 256
#define NBLK (BB / ROWS)          // 1024

// ---------------- SMEM layout ----------------
#define SM_B1Q 0                  // uint4[32 nt][2 ktp][32 lane]  32768
#define SM_B2Q 32768              // uint4[16 KT][4 ntp][32 lane]  32768
#define SM_QM  65536              // float2[256] = (cn2+eps, mu)    2048
#define SM_TOTAL 67584

static __device__ __forceinline__ uint32_t pack_bf16x2(float a, float b) {
    uint32_t r;
    asm("cvt.rn.bf16x2.f32 %0, %1, %2;" : "=r"(r) : "f"(b), "f"(a));
    return r;
}
static __device__ __forceinline__ void mma16816(
    float* c, uint32_t a0, uint32_t a1, uint32_t a2, uint32_t a3,
    uint32_t b0, uint32_t b1)
{
    asm volatile(
        "mma.sync.aligned.m16n8k16.row.col.f32.bf16.bf16.f32 "
        "{%0,%1,%2,%3}, {%4,%5,%6,%7}, {%8,%9}, {%0,%1,%2,%3};"
        : "+f"(c[0]), "+f"(c[1]), "+f"(c[2]), "+f"(c[3])
        : "r"(a0), "r"(a1), "r"(a2), "r"(a3), "r"(b0), "r"(b1));
}
static __device__ __forceinline__ float qred(float v) {
    v += __shfl_xor_sync(0xFFFFFFFFu, v, 1);
    v += __shfl_xor_sync(0xFFFFFFFFu, v, 2);
    return v;
}

__global__ void __launch_bounds__(THREADS, 2) pm_field_mma_kernel(
    const float* __restrict__ z_in,
    const float* __restrict__ centers,
    const float* __restrict__ mus,
    float* __restrict__ out)
{
    extern __shared__ char smem[];
    uint4* B1q = (uint4*)(smem + SM_B1Q);
    uint4* B2q = (uint4*)(smem + SM_B2Q);

    const int tid  = threadIdx.x;
    const int wid  = tid >> 5;
    const int lane = tid & 31;
    const int m    = lane & 3;
    const int g    = lane >> 2;

    // ---- setup: fragments straight from gmem ----
    for (int nt = 4 * wid; nt < 4 * wid + 4; nt++) {
        const float* p = centers + (8 * nt + g) * DD;
        #pragma unroll
        for (int ktp = 0; ktp < 2; ktp++) {
            const int d0 = 32 * ktp + 2 * m;
            float2 f0 = *(const float2*)(p + d0);
            float2 f1 = *(const float2*)(p + d0 + 8);
            float2 f2 = *(const float2*)(p + d0 + 16);
            float2 f3 = *(const float2*)(p + d0 + 24);
            uint4 v;
            v.x = pack_bf16x2(f0.x, f0.y);
            v.y = pack_bf16x2(f1.x, f1.y);
            v.z = pack_bf16x2(f2.x, f2.y);
            v.w = pack_bf16x2(f3.x, f3.y);
            B1q[(nt * 2 + ktp) * 32 + lane] = v;
        }
    }
    for (int KT = 2 * wid; KT < 2 * wid + 2; KT++) {
        const int c0 = 16 * KT + 2 * m;
        #pragma unroll
        for (int ntp = 0; ntp < 4; ntp++) {
            const int d0 = 16 * ntp + g;
            uint4 v;
            v.x = pack_bf16x2(centers[(c0    ) * DD + d0], centers[(c0 + 1) * DD + d0]);
            v.y = pack_bf16x2(centers[(c0 + 8) * DD + d0], centers[(c0 + 9) * DD + d0]);
            v.z = pack_bf16x2(centers[(c0    ) * DD + d0 + 8], centers[(c0 + 1) * DD + d0 + 8]);
            v.w = pack_bf16x2(centers[(c0 + 8) * DD + d0 + 8], centers[(c0 + 9) * DD + d0 + 8]);
            B2q[(KT * 4 + ntp) * 32 + lane] = v;
        }
    }
    {
        const int c = tid;   // THREADS == CC
        const float4* cr = (const float4*)(centers + c * DD);
        float s = 0.f;
        #pragma unroll
        for (int i = 0; i < DD / 4; i++) {
            float4 v = cr[i];
            s = fmaf(v.x, v.x, fmaf(v.y, v.y, fmaf(v.z, v.z, fmaf(v.w, v.w, s))));
        }
        *(float2*)(smem + SM_QM + c * 8) = make_float2(s + EPSV, mus[c]);
    }
    __syncthreads();
    // ==== no block syncs below — warps autonomous ====

    const size_t rbase = (size_t)blockIdx.x * ROWS + wid * 16 + g;
    float z0[16], z1[16];
    #pragma unroll
    for (int blk = 0; blk < 8; blk++) {
        float2 v;
        v = *(const float2*)(z_in + (rbase    ) * DD + 8 * blk + 2 * m); z0[2*blk]=v.x; z0[2*blk+1]=v.y;
        v = *(const float2*)(z_in + (rbase + 8) * DD + 8 * blk + 2 * m); z1[2*blk]=v.x; z1[2*blk+1]=v.y;
    }

    // constant ones B-fragment (column n=0): nonzero only on lanes with g==0
    const uint32_t bones = (g == 0) ? 0x3F803F80u : 0u;

    #pragma unroll 1
    for (int step = 0; step < NSTEP; step++) {
        float s0 = 0.f, s1 = 0.f;
        #pragma unroll
        for (int j = 0; j < 16; j++) {
            s0 = fmaf(z0[j], z0[j], s0);
            s1 = fmaf(z1[j], z1[j], s1);
        }
        s0 = qred(s0); s1 = qred(s1);

        uint32_t af[4][4];
        #pragma unroll
        for (int kt = 0; kt < 4; kt++) {
            af[kt][0] = pack_bf16x2(z0[4*kt+0], z0[4*kt+1]);
            af[kt][1] = pack_bf16x2(z1[4*kt+0], z1[4*kt+1]);
            af[kt][2] = pack_bf16x2(z0[4*kt+2], z0[4*kt+3]);
            af[kt][3] = pack_bf16x2(z1[4*kt+2], z1[4*kt+3]);
        }

        float gacc[8][4];
        #pragma unroll
        for (int i = 0; i < 8; i++)
            gacc[i][0] = gacc[i][1] = gacc[i][2] = gacc[i][3] = 0.f;
        float swacc[4] = {0.f, 0.f, 0.f, 0.f};   // Σw via W @ ones (tensor)
        float na0 = 0.f, na1 = 0.f;              // Σ(mu/r) scalar (fma pipe)

        // ---- prologue: GEMM1 for chunk 0 into aC ----
        float aC[2][4];
        {
            uint4 u0a = B1q[0 * 32 + lane];
            uint4 u0b = B1q[1 * 32 + lane];
            uint4 u1a = B1q[2 * 32 + lane];
            uint4 u1b = B1q[3 * 32 + lane];
            #pragma unroll
            for (int i = 0; i < 2; i++)
                aC[i][0] = aC[i][1] = aC[i][2] = aC[i][3] = 0.f;
            mma16816(aC[0], af[0][0], af[0][1], af[0][2], af[0][3], u0a.x, u0a.y);
            mma16816(aC[1], af[0][0], af[0][1], af[0][2], af[0][3], u1a.x, u1a.y);
            mma16816(aC[0], af[1][0], af[1][1], af[1][2], af[1][3], u0a.z, u0a.w);
            mma16816(aC[1], af[1][0], af[1][1], af[1][2], af[1][3], u1a.z, u1a.w);
            mma16816(aC[0], af[2][0], af[2][1], af[2][2], af[2][3], u0b.x, u0b.y);
            mma16816(aC[1], af[2][0], af[2][1], af[2][2], af[2][3], u1b.x, u1b.y);
            mma16816(aC[0], af[3][0], af[3][1], af[3][2], af[3][3], u0b.z, u0b.w);
            mma16816(aC[1], af[3][0], af[3][1], af[3][2], af[3][3], u1b.z, u1b.w);
        }

        #pragma unroll 1
        for (int KT = 0; KT < 16; KT++) {
            // B1 loads for NEXT chunk (LDS latency covered by the epilogue below)
            const int KTn = (KT < 15) ? (KT + 1) : 0;
            uint4 u0a = B1q[((2 * KTn    ) * 2 + 0) * 32 + lane];
            uint4 u0b = B1q[((2 * KTn    ) * 2 + 1) * 32 + lane];
            uint4 u1a = B1q[((2 * KTn + 1) * 2 + 0) * 32 + lane];
            uint4 u1b = B1q[((2 * KTn + 1) * 2 + 1) * 32 + lane];

            const int c0 = 16 * KT + 2 * m;
            const float4 q01 = *(const float4*)(smem + SM_QM + c0 * 8);
            const float4 q23 = *(const float4*)(smem + SM_QM + (c0 + 8) * 8);

            // ---- epilogue on aC (issued a full chunk ago — latency hidden) ----
            uint32_t wa[4];
            #pragma unroll
            for (int half = 0; half < 2; half++) {
                const float4 P = half ? q23 : q01;   // (cn2e_lo, mu_lo, cn2e_hi, mu_hi)
                float t0 = fmaf(-2.f, aC[half][0], s0 + P.x);
                float t1 = fmaf(-2.f, aC[half][1], s0 + P.z);
                float t2 = fmaf(-2.f, aC[half][2], s1 + P.x);
                float t3 = fmaf(-2.f, aC[half][3], s1 + P.z);
                float i0 = rsqrtf(t0), i1 = rsqrtf(t1), i2 = rsqrtf(t2), i3 = rsqrtf(t3);
                float m0 = P.y * i0, m1 = P.w * i1, m2 = P.y * i2, m3 = P.w * i3;
                na0 += m0 + m1;  na1 += m2 + m3;
                float w0 = m0*i0*i0, w1 = m1*i1*i1, w2 = m2*i2*i2, w3 = m3*i3*i3;
                wa[2*half]     = pack_bf16x2(w0, w1);
                wa[2*half + 1] = pack_bf16x2(w2, w3);
            }

            // ---- GEMM1 for next chunk into aN (independent of wa chain) ----
            float aN[2][4];
            #pragma unroll
            for (int i = 0; i < 2; i++)
                aN[i][0] = aN[i][1] = aN[i][2] = aN[i][3] = 0.f;
            mma16816(aN[0], af[0][0], af[0][1], af[0][2], af[0][3], u0a.x, u0a.y);
            mma16816(aN[1], af[0][0], af[0][1], af[0][2], af[0][3], u1a.x, u1a.y);
            mma16816(aN[0], af[1][0], af[1][1], af[1][2], af[1][3], u0a.z, u0a.w);
            mma16816(aN[1], af[1][0], af[1][1], af[1][2], af[1][3], u1a.z, u1a.w);
            mma16816(aN[0], af[2][0], af[2][1], af[2][2], af[2][3], u0b.x, u0b.y);
            mma16816(aN[1], af[2][0], af[2][1], af[2][2], af[2][3], u1b.x, u1b.y);
            mma16816(aN[0], af[3][0], af[3][1], af[3][2], af[3][3], u0b.z, u0b.w);
            mma16816(aN[1], af[3][0], af[3][1], af[3][2], af[3][3], u1b.z, u1b.w);

            // ---- GEMM2 of current chunk (wa ready; b2 LDS covered by GEMM1 issue) ----
            uint4 b2_0 = B2q[(KT * 4 + 0) * 32 + lane];
            uint4 b2_1 = B2q[(KT * 4 + 1) * 32 + lane];
            uint4 b2_2 = B2q[(KT * 4 + 2) * 32 + lane];
            uint4 b2_3 = B2q[(KT * 4 + 3) * 32 + lane];

            mma16816(swacc, wa[0], wa[1], wa[2], wa[3], bones, bones);
            mma16816(gacc[0], wa[0], wa[1], wa[2], wa[3], b2_0.x, b2_0.y);
            mma16816(gacc[1], wa[0], wa[1], wa[2], wa[3], b2_0.z, b2_0.w);
            mma16816(gacc[2], wa[0], wa[1], wa[2], wa[3], b2_1.x, b2_1.y);
            mma16816(gacc[3], wa[0], wa[1], wa[2], wa[3], b2_1.z, b2_1.w);
            mma16816(gacc[4], wa[0], wa[1], wa[2], wa[3], b2_2.x, b2_2.y);
            mma16816(gacc[5], wa[0], wa[1], wa[2], wa[3], b2_2.z, b2_2.w);
            mma16816(gacc[6], wa[0], wa[1], wa[2], wa[3], b2_3.x, b2_3.y);
            mma16816(gacc[7], wa[0], wa[1], wa[2], wa[3], b2_3.z, b2_3.w);

            // rotate accumulator buffers
            #pragma unroll
            for (int i = 0; i < 2; i++) {
                aC[i][0] = aN[i][0]; aC[i][1] = aN[i][1];
                aC[i][2] = aN[i][2]; aC[i][3] = aN[i][3];
            }
        }

        // reductions: sw from GEMM col 0 (broadcast), na scalar quad-reduce
        const int qbase = lane & 28;
        const float sw0 = __shfl_sync(0xFFFFFFFFu, swacc[0], qbase);
        const float sw1 = __shfl_sync(0xFFFFFFFFu, swacc[2], qbase);
        na0 = qred(na0);
        na1 = qred(na1);

        const float c0f = DTB / (1.f + na0);
        const float c1f = DTB / (1.f + na1);
        #pragma unroll
        for (int nt = 0; nt < 8; nt++) {
            float u;
            u = fmaf(c0f, fmaf(-sw0, z0[2*nt],   gacc[nt][0]), z0[2*nt]);   z0[2*nt]   = fminf(fmaxf(u,-3.f),3.f);
            u = fmaf(c0f, fmaf(-sw0, z0[2*nt+1], gacc[nt][1]), z0[2*nt+1]); z0[2*nt+1] = fminf(fmaxf(u,-3.f),3.f);
            u = fmaf(c1f, fmaf(-sw1, z1[2*nt],   gacc[nt][2]), z1[2*nt]);   z1[2*nt]   = fminf(fmaxf(u,-3.f),3.f);
            u = fmaf(c1f, fmaf(-sw1, z1[2*nt+1], gacc[nt][3]), z1[2*nt+1]); z1[2*nt+1] = fminf(fmaxf(u,-3.f),3.f);
        }
    }

    #pragma unroll
    for (int blk = 0; blk < 8; blk++) {
        *(float2*)(out + (rbase    ) * DD + 8*blk + 2*m) = make_float2(z0[2*blk], z0[2*blk+1]);
        *(float2*)(out + (rbase + 8) * DD + 8*blk + 2*m) = make_float2(z1[2*blk], z1[2*blk+1]);
    }
}

extern "C" void kernel_launch(void* const* d_in, const int* in_sizes, int n_in,
                              void* d_out, int out_size) {
    (void)in_sizes; (void)n_in; (void)out_size;
    const float* z       = (const float*)d_in[0];
    const float* centers = (const float*)d_in[1];
    const float* mus     = (const float*)d_in[2];
    float* out           = (float*)d_out;

    static bool attr_set = false;
    if (!attr_set) {
        cudaFuncSetAttribute(pm_field_mma_kernel,
                             cudaFuncAttributeMaxDynamicSharedMemorySize, SM_TOTAL);
        attr_set = true;
    }
    pm_field_mma_kernel<<<NBLK, THREADS, SM_TOTAL>>>(z, centers, mus, out);
}

// round 17
// speedup vs baseline: 1.3552x; 1.0646x over previous
#include <cuda_runtime.h>
#include <cuda_bf16.h>
#include <cstdint>

#define BB 131072
#define CC 256
#define DD 64
#define NSTEP 8
#define DTB 0.15f
#define EPSV 1e-4f
#define ROWS 128                  // per CTA (8 warps x 16 rows)
#define THREADS 256
#define NBLK (BB / ROWS)          // 1024

// ---------------- SMEM layout (FIXED: bmuq needs 4096 B, was 2048) ----------
#define SM_B1Q 0                  // uint4[32 nt][2 ktp][32 lane]  B1 = -2*centers   32768
#define SM_B2Q 32768              // uint4[16 KT][4 ntp][32 lane]  B2 = mu*centers   32768
#define SM_CNQ 65536              // uint32[32 nt][32 lane]  (cn2e_hi,cn2e_lo) m==0   4096
#define SM_BMU 69632              // uint2[16 KT][32 lane]   mu-column frag g==0      4096
#define SM_CN2E 73728             // float[256] scratch cn2+eps                       1024
#define SM_TOTAL 74752

static __device__ __forceinline__ uint32_t pack_bf16x2(float a, float b) {
    uint32_t r;
    asm("cvt.rn.bf16x2.f32 %0, %1, %2;" : "=r"(r) : "f"(b), "f"(a));
    return r;
}
static __device__ __forceinline__ void mma16816(
    float* c, uint32_t a0, uint32_t a1, uint32_t a2, uint32_t a3,
    uint32_t b0, uint32_t b1)
{
    asm volatile(
        "mma.sync.aligned.m16n8k16.row.col.f32.bf16.bf16.f32 "
        "{%0,%1,%2,%3}, {%4,%5,%6,%7}, {%8,%9}, {%0,%1,%2,%3};"
        : "+f"(c[0]), "+f"(c[1]), "+f"(c[2]), "+f"(c[3])
        : "r"(a0), "r"(a1), "r"(a2), "r"(a3), "r"(b0), "r"(b1));
}
static __device__ __forceinline__ float qred(float v) {
    v += __shfl_xor_sync(0xFFFFFFFFu, v, 1);
    v += __shfl_xor_sync(0xFFFFFFFFu, v, 2);
    return v;
}

__global__ void __launch_bounds__(THREADS, 2) pm_field_mma_kernel(
    const float* __restrict__ z_in,
    const float* __restrict__ centers,
    const float* __restrict__ mus,
    float* __restrict__ out)
{
    extern __shared__ char smem[];
    uint4*    B1q  = (uint4*)(smem + SM_B1Q);
    uint4*    B2q  = (uint4*)(smem + SM_B2Q);
    uint32_t* cnq  = (uint32_t*)(smem + SM_CNQ);
    uint2*    bmuq = (uint2*)(smem + SM_BMU);
    float*    cn2e = (float*)(smem + SM_CN2E);

    const int tid  = threadIdx.x;
    const int wid  = tid >> 5;
    const int lane = tid & 31;
    const int m    = lane & 3;
    const int g    = lane >> 2;

    // ---- phase 1: B1 (-2c), B2 (mu*c), mu-column frags, cn2e ----
    for (int nt = 4 * wid; nt < 4 * wid + 4; nt++) {
        const float* p = centers + (8 * nt + g) * DD;
        #pragma unroll
        for (int ktp = 0; ktp < 2; ktp++) {
            const int d0 = 32 * ktp + 2 * m;
            float2 f0 = *(const float2*)(p + d0);
            float2 f1 = *(const float2*)(p + d0 + 8);
            float2 f2 = *(const float2*)(p + d0 + 16);
            float2 f3 = *(const float2*)(p + d0 + 24);
            uint4 v;
            v.x = pack_bf16x2(-2.f * f0.x, -2.f * f0.y);
            v.y = pack_bf16x2(-2.f * f1.x, -2.f * f1.y);
            v.z = pack_bf16x2(-2.f * f2.x, -2.f * f2.y);
            v.w = pack_bf16x2(-2.f * f3.x, -2.f * f3.y);
            B1q[(nt * 2 + ktp) * 32 + lane] = v;
        }
    }
    for (int KT = 2 * wid; KT < 2 * wid + 2; KT++) {
        const int c0 = 16 * KT + 2 * m;
        const float muA0 = mus[c0],      muA1 = mus[c0 + 1];
        const float muB0 = mus[c0 + 8],  muB1 = mus[c0 + 9];
        #pragma unroll
        for (int ntp = 0; ntp < 4; ntp++) {
            const int d0 = 16 * ntp + g;
            uint4 v;
            v.x = pack_bf16x2(muA0 * centers[(c0    ) * DD + d0], muA1 * centers[(c0 + 1) * DD + d0]);
            v.y = pack_bf16x2(muB0 * centers[(c0 + 8) * DD + d0], muB1 * centers[(c0 + 9) * DD + d0]);
            v.z = pack_bf16x2(muA0 * centers[(c0    ) * DD + d0 + 8], muA1 * centers[(c0 + 1) * DD + d0 + 8]);
            v.w = pack_bf16x2(muB0 * centers[(c0 + 8) * DD + d0 + 8], muB1 * centers[(c0 + 9) * DD + d0 + 8]);
            B2q[(KT * 4 + ntp) * 32 + lane] = v;
        }
        // mu-column fragment (n=0 column => lanes g==0)
        uint2 bm = make_uint2(0u, 0u);
        if (g == 0) {
            bm.x = pack_bf16x2(muA0, muA1);
            bm.y = pack_bf16x2(muB0, muB1);
        }
        bmuq[KT * 32 + lane] = bm;
    }
    {
        const int c = tid;   // THREADS == CC
        const float4* cr = (const float4*)(centers + c * DD);
        float s = 0.f;
        #pragma unroll
        for (int i = 0; i < DD / 4; i++) {
            float4 v = cr[i];
            s = fmaf(v.x, v.x, fmaf(v.y, v.y, fmaf(v.z, v.z, fmaf(v.w, v.w, s))));
        }
        cn2e[c] = s + EPSV;
    }
    __syncthreads();

    // ---- phase 2: cn split fragments (phantom-tile B: k=8,9 slots -> m==0) ----
    for (int nt = 4 * wid; nt < 4 * wid + 4; nt++) {
        uint32_t v = 0u;
        if (m == 0) {
            float c2 = cn2e[8 * nt + g];
            float hi = __bfloat162float(__float2bfloat16(c2));
            v = pack_bf16x2(hi, c2 - hi);
        }
        cnq[nt * 32 + lane] = v;
    }
    __syncthreads();
    // ==== no block syncs below — warps autonomous ====

    const size_t rbase = (size_t)blockIdx.x * ROWS + wid * 16 + g;
    float z0[16], z1[16];
    #pragma unroll
    for (int blk = 0; blk < 8; blk++) {
        float2 v;
        v = *(const float2*)(z_in + (rbase    ) * DD + 8 * blk + 2 * m); z0[2*blk]=v.x; z0[2*blk+1]=v.y;
        v = *(const float2*)(z_in + (rbase + 8) * DD + 8 * blk + 2 * m); z1[2*blk]=v.x; z1[2*blk+1]=v.y;
    }

    // phantom-tile constants: A k=8,9 slots = 1 (m==0); B k=0,1 slots = 1 (m==0)
    const uint32_t onesm0 = (m == 0) ? 0x3F803F80u : 0u;

    #pragma unroll 1
    for (int step = 0; step < NSTEP; step++) {
        float s0 = 0.f, s1 = 0.f;
        #pragma unroll
        for (int j = 0; j < 16; j++) {
            s0 = fmaf(z0[j], z0[j], s0);
            s1 = fmaf(z1[j], z1[j], s1);
        }
        s0 = qred(s0); s1 = qred(s1);

        uint32_t af[4][4];
        #pragma unroll
        for (int kt = 0; kt < 4; kt++) {
            af[kt][0] = pack_bf16x2(z0[4*kt+0], z0[4*kt+1]);
            af[kt][1] = pack_bf16x2(z1[4*kt+0], z1[4*kt+1]);
            af[kt][2] = pack_bf16x2(z0[4*kt+2], z0[4*kt+3]);
            af[kt][3] = pack_bf16x2(z1[4*kt+2], z1[4*kt+3]);
        }
        // phantom-tile A: (zz_hi, zz_lo) at k=0,1 ; 1 at k=8,9  (m==0 lanes only)
        uint32_t afz0 = 0u, afz1 = 0u;
        if (m == 0) {
            float h0 = __bfloat162float(__float2bfloat16(s0));
            float h1 = __bfloat162float(__float2bfloat16(s1));
            afz0 = pack_bf16x2(h0, s0 - h0);
            afz1 = pack_bf16x2(h1, s1 - h1);
        }

        float gacc[8][4];
        #pragma unroll
        for (int i = 0; i < 8; i++)
            gacc[i][0] = gacc[i][1] = gacc[i][2] = gacc[i][3] = 0.f;
        float swacc[4] = {0.f, 0.f, 0.f, 0.f};   // Σ mu*v   via V @ mu-col
        float naacc[4] = {0.f, 0.f, 0.f, 0.f};   // Σ mu/r   via I @ mu-col

        #pragma unroll 2
        for (int KT = 0; KT < 16; KT++) {
            float aA[2][4];
            #pragma unroll
            for (int i = 0; i < 2; i++)
                aA[i][0] = aA[i][1] = aA[i][2] = aA[i][3] = 0.f;

            {   // GEMM1: acc = zz + cn2 + eps - 2*dot = r^2 + eps  (phantom tile last)
                uint4 u0a = B1q[((2 * KT    ) * 2 + 0) * 32 + lane];
                uint4 u0b = B1q[((2 * KT    ) * 2 + 1) * 32 + lane];
                uint4 u1a = B1q[((2 * KT + 1) * 2 + 0) * 32 + lane];
                uint4 u1b = B1q[((2 * KT + 1) * 2 + 1) * 32 + lane];
                uint32_t cn0 = cnq[(2 * KT    ) * 32 + lane];
                uint32_t cn1 = cnq[(2 * KT + 1) * 32 + lane];
                mma16816(aA[0], af[0][0], af[0][1], af[0][2], af[0][3], u0a.x, u0a.y);
                mma16816(aA[1], af[0][0], af[0][1], af[0][2], af[0][3], u1a.x, u1a.y);
                mma16816(aA[0], af[1][0], af[1][1], af[1][2], af[1][3], u0a.z, u0a.w);
                mma16816(aA[1], af[1][0], af[1][1], af[1][2], af[1][3], u1a.z, u1a.w);
                mma16816(aA[0], af[2][0], af[2][1], af[2][2], af[2][3], u0b.x, u0b.y);
                mma16816(aA[1], af[2][0], af[2][1], af[2][2], af[2][3], u1b.x, u1b.y);
                mma16816(aA[0], af[3][0], af[3][1], af[3][2], af[3][3], u0b.z, u0b.w);
                mma16816(aA[1], af[3][0], af[3][1], af[3][2], af[3][3], u1b.z, u1b.w);
                mma16816(aA[0], afz0, afz1, onesm0, onesm0, onesm0, cn0);
                mma16816(aA[1], afz0, afz1, onesm0, onesm0, onesm0, cn1);
            }

            // B2 + mu-col prefetch before epilogue (latency hides under rsqrt chain)
            uint4 b2_0 = B2q[(KT * 4 + 0) * 32 + lane];
            uint4 b2_1 = B2q[(KT * 4 + 1) * 32 + lane];
            uint4 b2_2 = B2q[(KT * 4 + 2) * 32 + lane];
            uint4 b2_3 = B2q[(KT * 4 + 3) * 32 + lane];
            uint2 bmu  = bmuq[KT * 32 + lane];

            // ---- epilogue: acc IS r^2+eps ; v = 1/r^3 , i = 1/r ----
            uint32_t va[4], ia[4];
            #pragma unroll
            for (int half = 0; half < 2; half++) {
                float i0 = rsqrtf(aA[half][0]);
                float i1 = rsqrtf(aA[half][1]);
                float i2 = rsqrtf(aA[half][2]);
                float i3 = rsqrtf(aA[half][3]);
                float v0 = (i0 * i0) * i0, v1 = (i1 * i1) * i1;
                float v2 = (i2 * i2) * i2, v3 = (i3 * i3) * i3;
                va[2*half]     = pack_bf16x2(v0, v1);
                va[2*half + 1] = pack_bf16x2(v2, v3);
                ia[2*half]     = pack_bf16x2(i0, i1);
                ia[2*half + 1] = pack_bf16x2(i2, i3);
            }

            // sums on tensor pipe (col 0): Σ mu*v, Σ mu*i
            mma16816(swacc, va[0], va[1], va[2], va[3], bmu.x, bmu.y);
            mma16816(naacc, ia[0], ia[1], ia[2], ia[3], bmu.x, bmu.y);

            // GEMM2: G += V @ (mu ⊙ centers)
            mma16816(gacc[0], va[0], va[1], va[2], va[3], b2_0.x, b2_0.y);
            mma16816(gacc[1], va[0], va[1], va[2], va[3], b2_0.z, b2_0.w);
            mma16816(gacc[2], va[0], va[1], va[2], va[3], b2_1.x, b2_1.y);
            mma16816(gacc[3], va[0], va[1], va[2], va[3], b2_1.z, b2_1.w);
            mma16816(gacc[4], va[0], va[1], va[2], va[3], b2_2.x, b2_2.y);
            mma16816(gacc[5], va[0], va[1], va[2], va[3], b2_2.z, b2_2.w);
            mma16816(gacc[6], va[0], va[1], va[2], va[3], b2_3.x, b2_3.y);
            mma16816(gacc[7], va[0], va[1], va[2], va[3], b2_3.z, b2_3.w);
        }

        // broadcast col-0 sums within quad
        const int qbase = lane & 28;
        const float sw0 = __shfl_sync(0xFFFFFFFFu, swacc[0], qbase);
        const float sw1 = __shfl_sync(0xFFFFFFFFu, swacc[2], qbase);
        const float na0 = __shfl_sync(0xFFFFFFFFu, naacc[0], qbase);
        const float na1 = __shfl_sync(0xFFFFFFFFu, naacc[2], qbase);

        const float c0f = DTB / (1.f + na0);
        const float c1f = DTB / (1.f + na1);
        #pragma unroll
        for (int nt = 0; nt < 8; nt++) {
            float u;
            u = fmaf(c0f, fmaf(-sw0, z0[2*nt],   gacc[nt][0]), z0[2*nt]);   z0[2*nt]   = fminf(fmaxf(u,-3.f),3.f);
            u = fmaf(c0f, fmaf(-sw0, z0[2*nt+1], gacc[nt][1]), z0[2*nt+1]); z0[2*nt+1] = fminf(fmaxf(u,-3.f),3.f);
            u = fmaf(c1f, fmaf(-sw1, z1[2*nt],   gacc[nt][2]), z1[2*nt]);   z1[2*nt]   = fminf(fmaxf(u,-3.f),3.f);
            u = fmaf(c1f, fmaf(-sw1, z1[2*nt+1], gacc[nt][3]), z1[2*nt+1]); z1[2*nt+1] = fminf(fmaxf(u,-3.f),3.f);
        }
    }

    #pragma unroll
    for (int blk = 0; blk < 8; blk++) {
        *(float2*)(out + (rbase    ) * DD + 8*blk + 2*m) = make_float2(z0[2*blk], z0[2*blk+1]);
        *(float2*)(out + (rbase + 8) * DD + 8*blk + 2*m) = make_float2(z1[2*blk], z1[2*blk+1]);
    }
}

extern "C" void kernel_launch(void* const* d_in, const int* in_sizes, int n_in,
                              void* d_out, int out_size) {
    (void)in_sizes; (void)n_in; (void)out_size;
    const float* z       = (const float*)d_in[0];
    const float* centers = (const float*)d_in[1];
    const float* mus     = (const float*)d_in[2];
    float* out           = (float*)d_out;

    static bool attr_set = false;
    if (!attr_set) {
        cudaFuncSetAttribute(pm_field_mma_kernel,
                             cudaFuncAttributeMaxDynamicSharedMemorySize, SM_TOTAL);
        attr_set = true;
    }
    pm_field_mma_kernel<<<NBLK, THREADS, SM_TOTAL>>>(z, centers, mus, out);
}